// round 17
// baseline (speedup 1.0000x reference)
#include <cuda_runtime.h>
#include <math.h>

#define DD 2048
#define LL 128
#define BB 64
#define NTHR 256
#define WPB (NTHR / 32)            // 8 warps per block -> 8 rows per block
#define NBLK (BB * LL / WPB)       // 1024 blocks
#define BLK_PER_B (LL / WPB)       // 16 blocks per batch
#define TRI (LL * (LL - 1) / 2)    // 8128 pairs in full triangle

// Scratch (no device allocation allowed)
__device__ float    g_dj[BB * LL];
__device__ float    g_ek[BB * LL];
__device__ float    g_bsum[BB];
__device__ int      g_pcnt[BB];
__device__ unsigned g_bdone[BB];   // per-batch monotonic counters (replay-safe)
__device__ unsigned g_done;        // global monotonic counter

// Fast softplus: MUFU-based. |err| ~1e-6 vs 1e-3 tolerance.
__device__ __forceinline__ float softplus_fast(float x) {
    return fmaxf(x, 0.f) + __logf(1.f + __expf(-fabsf(x)));
}

// ---------------------------------------------------------------------------
// Single fused kernel.
//  Stage A (all 1024 blocks): 8-row dual dot products — the 67 MB HBM stream
//    (proven config: 4 blocks/SM, 8-deep staged __ldcs, ~6.7 TB/s).
//  Stage B (one block per batch — the 16th to finish): pair softplus sweep
//    for that batch, overlapped with other batches' Stage A.
//  Stage C (globally last batch-finisher): tree-reduce 64 sums -> out.
// No barriers, no spins: dependency tracked by monotonic counters only.
// ---------------------------------------------------------------------------
__global__ __launch_bounds__(NTHR, 4) void dli_kernel(
    const float* __restrict__ enc,   // [64,128,2048]
    const int*   __restrict__ mask,  // [64,128]
    const float* __restrict__ W,     // [4096,2] row-major
    const float* __restrict__ bias,  // [2]
    float* __restrict__ out)
{
    __shared__ float s_wl[DD];
    __shared__ float s_wr[DD];
    __shared__ float s_dj[LL];
    __shared__ float s_ek[LL];
    __shared__ float s_mred[4];
    __shared__ float s_wred[WPB];
    __shared__ int   s_do, s_fin;

    const int tid  = threadIdx.x;
    const int blk  = blockIdx.x;
    const int b    = blk / BLK_PER_B;     // this block's batch
    const int warp = tid >> 5;
    const int lane = tid & 31;

    // ---- Stage A: column-diff weights + 8-row dot products ----------------
    for (int d = tid; d < DD; d += NTHR) {
        float2 a = *(const float2*)(W + 2 * d);
        float2 r = *(const float2*)(W + 2 * (DD + d));
        s_wl[d] = a.y - a.x;
        s_wr[d] = r.y - r.x;
    }
    __syncthreads();

    {
        const int row = blk * WPB + warp;
        const float4* e4  = (const float4*)(enc + (size_t)row * DD);
        const float4* wl4 = (const float4*)s_wl;
        const float4* wr4 = (const float4*)s_wr;

        float sd = 0.f, se = 0.f;
#pragma unroll
        for (int half = 0; half < 2; ++half) {
            float4 e[8];
#pragma unroll
            for (int it = 0; it < 8; ++it)
                e[it] = __ldcs(&e4[lane + (half * 8 + it) * 32]);
#pragma unroll
            for (int it = 0; it < 8; ++it) {
                int i = lane + (half * 8 + it) * 32;
                float4 a = wl4[i];
                float4 r = wr4[i];
                sd += e[it].x * a.x + e[it].y * a.y + e[it].z * a.z + e[it].w * a.w;
                se += e[it].x * r.x + e[it].y * r.y + e[it].z * r.z + e[it].w * r.w;
            }
        }
#pragma unroll
        for (int o = 16; o; o >>= 1) {
            sd += __shfl_down_sync(0xFFFFFFFFu, sd, o);
            se += __shfl_down_sync(0xFFFFFFFFu, se, o);
        }
        if (lane == 0) {
            __stcg(&g_dj[row], sd);    // straight to L2: cross-SM consumers
            __stcg(&g_ek[row], se);
        }
    }

    // ---- Batch completion: 16th-arriving block runs the pair sweep --------
    __syncthreads();                     // all 8 warps' dj/ek stores done
    if (tid == 0) {
        __threadfence();                 // cumulative: block's stores -> device
        unsigned o1 = atomicAdd(&g_bdone[b], 1u);
        s_do  = ((o1 % (unsigned)BLK_PER_B) == (unsigned)(BLK_PER_B - 1));
        s_fin = 0;
    }
    __syncthreads();
    if (!s_do) return;

    // ---- Stage B: pair softplus sweep for batch b --------------------------
    __threadfence();                     // acquire side of the counter
    if (tid < LL) {
        int v = mask[b * LL + tid];
#pragma unroll
        for (int o = 16; o; o >>= 1)
            v += __shfl_down_sync(0xFFFFFFFFu, v, o);
        if (lane == 0) s_mred[tid >> 5] = (float)v;
        s_dj[tid] = __ldcg(&g_dj[b * LL + tid]);   // L2 read: skip stale L1
        s_ek[tid] = __ldcg(&g_ek[b * LL + tid]);
    }
    __syncthreads();

    const int   len = (int)(s_mred[0] + s_mred[1] + s_mred[2] + s_mred[3] + 0.5f);
    const float db  = bias[1] - bias[0];

    float acc = 0.f;
#pragma unroll
    for (int s = 0; s < (TRI + NTHR - 1) / NTHR; ++s) {   // 32 iterations
        int idx = tid + s * NTHR;
        if (idx < TRI) {
            int j = (int)((1.0f + sqrtf(1.0f + 8.0f * (float)idx)) * 0.5f);
            while (j * (j - 1) / 2 > idx) --j;
            while ((j + 1) * j / 2 <= idx) ++j;
            int k = idx - j * (j - 1) / 2;
            float x = s_dj[j] + s_ek[k] + db;
            if (k == j - 1) x = -x;      // label 1 -> softplus(-(z1-z0))
            if (j < len) acc += softplus_fast(x);
        }
    }
#pragma unroll
    for (int o = 16; o; o >>= 1)
        acc += __shfl_down_sync(0xFFFFFFFFu, acc, o);
    if (lane == 0) s_wred[warp] = acc;
    __syncthreads();

    if (tid == 0) {
        float v = 0.f;
#pragma unroll
        for (int w = 0; w < WPB; ++w) v += s_wred[w];
        __stcg(&g_bsum[b], v);
        __stcg(&g_pcnt[b], len * (len - 1) / 2);
        __threadfence();
        unsigned o2 = atomicAdd(&g_done, 1u);
        s_fin = ((o2 % (unsigned)BB) == (unsigned)(BB - 1));
    }
    __syncthreads();
    if (!s_fin) return;

    // ---- Stage C: final reduce of 64 batch sums ----------------------------
    __threadfence();
    {
        float v = (tid < BB) ? __ldcg(&g_bsum[tid]) : 0.f;
        int   c = (tid < BB) ? __ldcg(&g_pcnt[tid]) : 0;
#pragma unroll
        for (int o = 16; o; o >>= 1) {
            v += __shfl_down_sync(0xFFFFFFFFu, v, o);
            c += __shfl_down_sync(0xFFFFFFFFu, c, o);
        }
        if (tid < BB && lane == 0) {
            s_wred[tid >> 5] = v;
            s_mred[tid >> 5] = (float)c;
        }
    }
    __syncthreads();
    if (tid == 0) {
        float sum = s_wred[0] + s_wred[1];
        int   cnt = (int)(s_mred[0] + s_mred[1] + 0.5f);
        if (cnt < 1) cnt = 1;
        out[0] = sum / (float)cnt;
    }
}

extern "C" void kernel_launch(void* const* d_in, const int* in_sizes, int n_in,
                              void* d_out, int out_size) {
    const float* enc  = (const float*)d_in[0];  // [64,128,2048] f32
    const int*   mask = (const int*)d_in[1];    // [64,128] i32
    const float* W    = (const float*)d_in[2];  // [4096,2] f32
    const float* bias = (const float*)d_in[3];  // [2] f32
    float* out = (float*)d_out;

    dli_kernel<<<NBLK, NTHR>>>(enc, mask, W, bias, out);
}